// round 9
// baseline (speedup 1.0000x reference)
#include <cuda_runtime.h>
#include <cuda.h>
#include <cuda_bf16.h>
#include <stdint.h>
#include <math.h>

typedef unsigned int u32;
typedef unsigned short u16;
typedef unsigned long long u64t;

// Fixed problem shape
#define NROWS 8192
#define DIM   128
#define BCLS  64
#define RBLK  128          // rows per block (one class per block)
#define CTILE 128          // cols per tile
#define NCHALF 2
#define CHALF (NROWS/NCHALF)           // 4096
#define NTILES (CHALF/CTILE)           // 32
#define NBUF  6
#define TILEB 16384        // fp8 tile bytes: 128 rows x 128B

__device__ __align__(256) unsigned char g_feat8[NROWS * DIM];   // normalized, e4m3
__device__ __align__(64) CUtensorMap g_mapF;
__device__ float g_all[NCHALF][2][NROWS];
__device__ float g_pos[NCHALF][2][NROWS];

// ---------------------------------------------------------------------------
// PTX helpers
// ---------------------------------------------------------------------------
__device__ __forceinline__ u32 smem_u32(const void* p) {
    return (u32)__cvta_generic_to_shared(p);
}
__device__ __forceinline__ void mbar_init(u32 addr, u32 cnt) {
    asm volatile("mbarrier.init.shared.b64 [%0], %1;" :: "r"(addr), "r"(cnt) : "memory");
}
__device__ __forceinline__ void mbar_expect(u32 addr, u32 bytes) {
    asm volatile("mbarrier.arrive.expect_tx.shared.b64 _, [%0], %1;"
                 :: "r"(addr), "r"(bytes) : "memory");
}
__device__ __forceinline__ void mbar_arrive(u32 addr) {
    asm volatile("mbarrier.arrive.shared.b64 _, [%0];" :: "r"(addr) : "memory");
}
__device__ __forceinline__ void mbar_wait(u32 addr, u32 parity) {
    asm volatile("{\n\t.reg .pred P1;\n\t"
                 "WAIT_LP_%=:\n\t"
                 "mbarrier.try_wait.parity.acquire.cta.shared::cta.b64 P1, [%0], %1, 0x989680;\n\t"
                 "@P1 bra.uni WAIT_DN_%=;\n\t"
                 "bra.uni WAIT_LP_%=;\n\t"
                 "WAIT_DN_%=:\n\t}"
                 :: "r"(addr), "r"(parity) : "memory");
}
__device__ __forceinline__ void tma2d(u32 dst, const void* map, int cx, int cy, u32 mbar) {
    asm volatile("cp.async.bulk.tensor.2d.shared::cta.global.tile.mbarrier::complete_tx::bytes "
                 "[%0], [%1, {%2, %3}], [%4];"
                 :: "r"(dst), "l"(map), "r"(cx), "r"(cy), "r"(mbar) : "memory");
}
__device__ __forceinline__ void ldsm4(u32& q0, u32& q1, u32& q2, u32& q3, u32 addr) {
    asm volatile("ldmatrix.sync.aligned.m8n8.x4.shared.b16 {%0,%1,%2,%3}, [%4];"
                 : "=r"(q0), "=r"(q1), "=r"(q2), "=r"(q3) : "r"(addr));
}
__device__ __forceinline__ void mma_fp8(float* dacc, u32 qa0, u32 qa1, u32 qa2, u32 qa3,
                                        u32 qb0, u32 qb1) {
    asm volatile("mma.sync.aligned.m16n8k32.row.col.f32.e4m3.e4m3.f32 "
                 "{%0,%1,%2,%3}, {%4,%5,%6,%7}, {%8,%9}, {%0,%1,%2,%3};"
                 : "+f"(dacc[0]), "+f"(dacc[1]), "+f"(dacc[2]), "+f"(dacc[3])
                 : "r"(qa0), "r"(qa1), "r"(qa2), "r"(qa3), "r"(qb0), "r"(qb1));
}
__device__ __forceinline__ float ex2f(float v) {
    float r;
    asm("ex2.approx.f32 %0, %1;" : "=f"(r) : "f"(v));
    return r;
}

// ---------------------------------------------------------------------------
// Kernel 1: L2-normalize rows (fp32 math), emit e4m3 [8192][128] (128B/row)
// ---------------------------------------------------------------------------
__global__ __launch_bounds__(256) void normalize_kernel(const float* __restrict__ x) {
    int gw   = (blockIdx.x * 256 + threadIdx.x) >> 5;
    int lane = threadIdx.x & 31;
    float4 v = ((const float4*)(x + (size_t)gw * DIM))[lane];
    float ss = v.x * v.x + v.y * v.y + v.z * v.z + v.w * v.w;
    #pragma unroll
    for (int o = 16; o; o >>= 1) ss += __shfl_xor_sync(0xffffffffu, ss, o);
    float inv = 1.0f / fmaxf(sqrtf(ss), 1e-12f);
    u16 p01, p23;
    asm("cvt.rn.satfinite.e4m3x2.f32 %0, %1, %2;" : "=h"(p01)
        : "f"(v.y * inv), "f"(v.x * inv));
    asm("cvt.rn.satfinite.e4m3x2.f32 %0, %1, %2;" : "=h"(p23)
        : "f"(v.w * inv), "f"(v.z * inv));
    u32 word = (u32)p01 | ((u32)p23 << 16);
    ((u32*)(g_feat8 + (size_t)gw * DIM))[lane] = word;
}

// ---------------------------------------------------------------------------
// Kernel 2: TMA + fp8 mma.sync, software-pipelined groups.
// Grid (2, 64). 512 threads = 16 warps: rg = w>>1 (16 rows), cg = w&1 (64 cols).
// Per tile: 4 B-groups of 16 n-rows; epilogue of group i-1 overlaps MMA of
// group i. Per-warp group rotation de-phases warps. A fragments hoisted.
// ---------------------------------------------------------------------------

// Epilogue for one group: ac[0..7] -> sums. nb0/nb1 = mask rows.
#define EPI(ac, ppq) do {                                                     \
    const int nb0q = 2 * (ppq), nb1q = nb0q + 1;                              \
    float e0 = ex2f(fmaf((ac)[0], L2E, -L2E));                                \
    float e1 = ex2f(fmaf((ac)[1], L2E, -L2E));                                \
    float e2 = ex2f(fmaf((ac)[2], L2E, -L2E));                                \
    float e3 = ex2f(fmaf((ac)[3], L2E, -L2E));                                \
    float e4 = ex2f(fmaf((ac)[4], L2E, -L2E));                                \
    float e5 = ex2f(fmaf((ac)[5], L2E, -L2E));                                \
    float e6 = ex2f(fmaf((ac)[6], L2E, -L2E));                                \
    float e7 = ex2f(fmaf((ac)[7], L2E, -L2E));                                \
    sa0 += e0 + e1; sa1 += e2 + e3;                                           \
    sa0 += e4 + e5; sa1 += e6 + e7;                                           \
    sp0 = fmaf(e0, mf[nb0q][0], sp0); sp0 = fmaf(e1, mf[nb0q][1], sp0);       \
    sp1 = fmaf(e2, mf[nb0q][0], sp1); sp1 = fmaf(e3, mf[nb0q][1], sp1);       \
    sp0 = fmaf(e4, mf[nb1q][0], sp0); sp0 = fmaf(e5, mf[nb1q][1], sp0);       \
    sp1 = fmaf(e6, mf[nb1q][0], sp1); sp1 = fmaf(e7, mf[nb1q][1], sp1);       \
} while (0)

// One group: ldsm 4 B frags + 8 mma into ac. last==1 -> release buffer.
#define GROUP(ac, ppq, last) do {                                             \
    const u32 gb = bB + baseB + (u32)(ppq) * 2048u;                           \
    u32 qb0[4], qb1[4], qb2[4], qb3[4];                                       \
    _Pragma("unroll")                                                         \
    for (int s = 0; s < 4; s++) {                                             \
        const u32 ch = (u32)(2 * s) + hi;                                     \
        ldsm4(qb0[s], qb1[s], qb2[s], qb3[s], gb + ((ch ^ sw) << 4));         \
    }                                                                         \
    if ((last) && lane == 0) mbar_arrive(relb[b]);                            \
    _Pragma("unroll")                                                         \
    for (int s = 0; s < 4; s++) {                                             \
        (ac)[0] = (ac)[0]; /* no-op keeps macro hygiene */                    \
        mma_fp8((ac),     qa0[s], qa1[s], qa2[s], qa3[s], qb0[s], qb2[s]);    \
        mma_fp8((ac) + 4, qa0[s], qa1[s], qa2[s], qa3[s], qb1[s], qb3[s]);    \
    }                                                                         \
} while (0)

__global__ __launch_bounds__(512) void fused_fp8_kernel(const int* __restrict__ y) {
    extern __shared__ __align__(1024) char smem[];
    const u32 sA = smem_u32(smem);            // 16KB
    const u32 sB = sA + TILEB;                // 6 x 16KB ring

    __shared__ __align__(8) u64t full_sh[NBUF];
    __shared__ __align__(8) u64t rel_sh[NBUF];
    __shared__ int ys[BCLS];

    const int tid  = threadIdx.x;
    const int lane = tid & 31;
    const int w    = tid >> 5;
    const int rg   = w >> 1;
    const int cg   = w & 1;
    const int rowblk = blockIdx.y;
    const int chalf  = blockIdx.x;
    const int colrow0 = chalf * CHALF;
    const int myclass = __ldg(y + rowblk);

    u32 fullb[NBUF], relb[NBUF];
    #pragma unroll
    for (int i = 0; i < NBUF; i++) {
        fullb[i] = smem_u32(&full_sh[i]);
        relb[i]  = smem_u32(&rel_sh[i]);
    }

    if (tid < BCLS) ys[tid] = y[tid];
    if (tid == 0) {
        #pragma unroll
        for (int i = 0; i < NBUF; i++) { mbar_init(fullb[i], 1); mbar_init(relb[i], 16); }
    }
    __syncthreads();

    const CUtensorMap* mp = &g_mapF;
    if (tid == 0) {
        asm volatile("prefetch.tensormap [%0];" :: "l"(mp));
        mbar_expect(fullb[0], 2 * TILEB);
        tma2d(sA, mp, 0, rowblk * RBLK, fullb[0]);
        tma2d(sB, mp, 0, colrow0, fullb[0]);
        #pragma unroll
        for (int bq = 1; bq < NBUF; bq++) {
            mbar_expect(fullb[bq], TILEB);
            tma2d(sB + (u32)(bq * TILEB), mp, 0, colrow0 + bq * CTILE, fullb[bq]);
        }
    }

    // mask table: col%64 = nb*8 + 2*(lane&3) + bb
    float mf[8][2];
    #pragma unroll
    for (int nb = 0; nb < 8; nb++) {
        int c0 = nb * 8 + 2 * (lane & 3);
        mf[nb][0] = (ys[c0]     == myclass) ? 1.0f : 0.0f;
        mf[nb][1] = (ys[c0 + 1] == myclass) ? 1.0f : 0.0f;
    }

    // ldmatrix addressing (fp8, 128B rows). swizzle term = lrow&7 for A and B
    // (row offsets rg*16 / cg*64 / pp*16 are all 0 mod 8).
    const int lrow = lane & 15;
    const u32 hi   = (u32)(lane >> 4);
    const u32 sw   = (u32)(lrow & 7);
    const u32 offA  = (u32)((rg * 16 + lrow) * 128);
    const u32 baseB = (u32)((cg * 64 + lrow) * 128);
    const int rot   = w & 3;   // per-warp group rotation

    // Hoist A fragments (loop-invariant): wait buf0 (A + B0), load 4 s-steps.
    mbar_wait(fullb[0], 0);
    u32 qa0[4], qa1[4], qa2[4], qa3[4];
    #pragma unroll
    for (int s = 0; s < 4; s++) {
        const u32 ch = (u32)(2 * s) + hi;
        ldsm4(qa0[s], qa1[s], qa2[s], qa3[s], sA + offA + ((ch ^ sw) << 4));
    }

    const float L2E = 1.4426950408889634f;
    float sa0 = 0.f, sa1 = 0.f, sp0 = 0.f, sp1 = 0.f;

    for (int t = 0; t < NTILES; t++) {
        const int b = t % NBUF;
        mbar_wait(fullb[b], (u32)((t / NBUF) & 1));
        const u32 bB = sB + (u32)(b * TILEB);

        float acc0[8], acc1[8];
        #pragma unroll
        for (int q = 0; q < 8; q++) { acc0[q] = 0.f; acc1[q] = 0.f; }

        const int p0 = rot, p1 = (rot + 1) & 3, p2 = (rot + 2) & 3, p3 = (rot + 3) & 3;

        GROUP(acc0, p0, 0);
        GROUP(acc1, p1, 0);  EPI(acc0, p0);
        #pragma unroll
        for (int q = 0; q < 8; q++) acc0[q] = 0.f;
        GROUP(acc0, p2, 0);  EPI(acc1, p1);
        #pragma unroll
        for (int q = 0; q < 8; q++) acc1[q] = 0.f;
        GROUP(acc1, p3, 1);  EPI(acc0, p2);

        // producer: refill buffer b for tile t+NBUF once all 16 warps released
        if (tid == 0 && t + NBUF < NTILES) {
            mbar_wait(relb[b], (u32)((t / NBUF) & 1));
            mbar_expect(fullb[b], TILEB);
            tma2d(sB + (u32)(b * TILEB), mp, 0, colrow0 + (t + NBUF) * CTILE, fullb[b]);
        }

        EPI(acc1, p3);
    }

    // quad reduce (4 lanes share a row)
    #pragma unroll
    for (int o = 1; o <= 2; o <<= 1) {
        sa0 += __shfl_xor_sync(0xffffffffu, sa0, o);
        sa1 += __shfl_xor_sync(0xffffffffu, sa1, o);
        sp0 += __shfl_xor_sync(0xffffffffu, sp0, o);
        sp1 += __shfl_xor_sync(0xffffffffu, sp1, o);
    }
    if ((lane & 3) == 0) {
        int r = rowblk * RBLK + rg * 16 + (lane >> 2);
        g_all[chalf][cg][r]     = sa0;
        g_pos[chalf][cg][r]     = sp0;
        g_all[chalf][cg][r + 8] = sa1;
        g_pos[chalf][cg][r + 8] = sp1;
    }
}

// ---------------------------------------------------------------------------
// Kernel 3: per-row loss, deterministic tree reduce, mean.
// ---------------------------------------------------------------------------
__global__ __launch_bounds__(1024) void finalize_kernel(float* __restrict__ out) {
    __shared__ float red[1024];
    int t = threadIdx.x;
    float s = 0.f;
    #pragma unroll
    for (int i = 0; i < 8; i++) {
        int r = t * 8 + i;
        float all = g_all[0][0][r] + g_all[0][1][r] + g_all[1][0][r] + g_all[1][1][r];
        float pos = g_pos[0][0][r] + g_pos[0][1][r] + g_pos[1][0][r] + g_pos[1][1][r];
        s += -logf(pos / (all + 1e-8f) + 1e-8f);
    }
    red[t] = s;
    __syncthreads();
    #pragma unroll
    for (int o = 512; o; o >>= 1) {
        if (t < o) red[t] += red[t + o];
        __syncthreads();
    }
    if (t == 0) out[0] = red[0] / (float)NROWS;
}

// ---------------------------------------------------------------------------
// Host
// ---------------------------------------------------------------------------
typedef CUresult (*EncFn)(CUtensorMap*, CUtensorMapDataType, cuuint32_t, void*,
                          const cuuint64_t*, const cuuint64_t*, const cuuint32_t*,
                          const cuuint32_t*, CUtensorMapInterleave, CUtensorMapSwizzle,
                          CUtensorMapL2promotion, CUtensorMapFloatOOBfill);

extern "C" void kernel_launch(void* const* d_in, const int* in_sizes, int n_in,
                              void* d_out, int out_size) {
    const float* x = (const float*)d_in[0];   // [64,128,128] f32
    const int*   y = (const int*)d_in[1];     // [64] i32
    float* out = (float*)d_out;

    static CUtensorMap h_map;
    static int inited = 0;
    const int dyn_smem = (1 + NBUF) * TILEB;   // 112 KB
    if (!inited) {
        cudaFuncSetAttribute(fused_fp8_kernel,
                             cudaFuncAttributeMaxDynamicSharedMemorySize, dyn_smem);
        void* fptr = 0;
        cudaDriverEntryPointQueryResult qr;
        cudaGetDriverEntryPoint("cuTensorMapEncodeTiled", &fptr,
                                cudaEnableDefault, &qr);
        void* dfeat = 0;
        cudaGetSymbolAddress(&dfeat, g_feat8);
        cuuint64_t dims[2]    = {DIM, NROWS};
        cuuint64_t strides[1] = {DIM};
        cuuint32_t box[2]     = {DIM, RBLK};
        cuuint32_t es[2]      = {1, 1};
        ((EncFn)fptr)(&h_map, CU_TENSOR_MAP_DATA_TYPE_UINT8, 2, dfeat,
                      dims, strides, box, es,
                      CU_TENSOR_MAP_INTERLEAVE_NONE, CU_TENSOR_MAP_SWIZZLE_128B,
                      CU_TENSOR_MAP_L2_PROMOTION_L2_128B,
                      CU_TENSOR_MAP_FLOAT_OOB_FILL_NONE);
        inited = 1;
    }

    cudaMemcpyToSymbolAsync(g_mapF, &h_map, sizeof(CUtensorMap), 0,
                            cudaMemcpyHostToDevice, 0);
    normalize_kernel<<<NROWS / 8, 256>>>(x);
    fused_fp8_kernel<<<dim3(NCHALF, NROWS / RBLK), 512, dyn_smem>>>(y);
    finalize_kernel<<<1, 1024>>>(out);
}